// round 6
// baseline (speedup 1.0000x reference)
#include <cuda_runtime.h>
#include <cstdint>

// MSPushPullLoss — round 5.
// Round-4 regression: fused epilogue pushed pass kernels to 40 regs / 24KB smem
// -> occ 64% -> pass2 46.7us. Fixes: __launch_bounds__(256,8) (cap 32 regs,
// epilogue doubles spill — runs once), epilogue smem UNIONed onto bins,
// 8192-px chunks (grid 2688) for finer SM load balancing.
// Keeps: reverse-walk pass2 (L2 reuse), 2-launch tail-CTA fusion,
// integer fixed-point accumulation (bit-deterministic across graph replays).

#define NSEG 272                  // 16 batches * 17 labels (0..16)
#define CNT_BITS 21
#define CNT_MASK ((1ll << CNT_BITS) - 1)
#define FPSCALE_F 16384.0f        // q14 fixed point
#define FPSCALE_D 16384.0
#define NCTA 2688                 // 2048 + 512 + 128 chunks of 8192 px

__device__ unsigned long long g_bins1[3 * NSEG];  // packed (sum_q14<<21 | count)
__device__ unsigned long long g_bins2[3 * NSEG];  // pull sum_q14
__device__ float g_mean[NSEG];
__device__ int g_cnt1;            // tail-CTA election counters (self-resetting)
__device__ int g_cnt2;

// ---------------------------------------------------------------------------
struct Map {
    const float4* f;
    const int4* g;
    int scale;
    size_t base4;   // float4 index of 2048-float4 chunk start
    int batch;
};

__device__ __forceinline__ Map decode(const float* f0, const float* f1, const float* f2,
                                      const int* g0, const int* g1, const int* g2) {
    Map m;
    int cid = blockIdx.x;
    if (cid < 2048) {                       // scale0: 128 chunks/batch
        m.scale = 0; m.f = (const float4*)f0; m.g = (const int4*)g0;
        m.batch = cid >> 7;
        m.base4 = (size_t)m.batch * (1u << 18) + (size_t)(cid & 127) * 2048u;
    } else if (cid < 2560) {                // scale1: 32 chunks/batch
        int c = cid - 2048;
        m.scale = 1; m.f = (const float4*)f1; m.g = (const int4*)g1;
        m.batch = c >> 5;
        m.base4 = (size_t)m.batch * (1u << 16) + (size_t)(c & 31) * 2048u;
    } else {                                // scale2: 8 chunks/batch
        int c = cid - 2560;
        m.scale = 2; m.f = (const float4*)f2; m.g = (const int4*)g2;
        m.batch = c >> 3;
        m.base4 = (size_t)m.batch * (1u << 14) + (size_t)(c & 7) * 2048u;
    }
    return m;
}

// Shared-memory overlay: bins for the hot loop, epilogue arrays afterwards.
union SmemU {
    int bins[17][256];                      // 17408 B
    struct {
        double s_pull[NSEG];
        double redv[256];
        float s_mean[NSEG];
        int redn[256];
        unsigned char s_pres[NSEG];
    } epi;                                  // ~6608 B
};

// ---------------------------------------------------------------------------
__device__ __forceinline__ void acc1px(int* mybin, float xv, int gg) {
    unsigned row = min((unsigned)(gg - 1), 16u);   // row 16 = invalid dump
    int q = __float2int_rn(xv * FPSCALE_F);
    mybin[row << 8] += q * 128 + 1;                // (q<<7) | count (<=32/thread)
}

__device__ __forceinline__ void acc1v(int* mybin, float4 x, int4 g) {
    acc1px(mybin, x.x, g.x); acc1px(mybin, x.y, g.y);
    acc1px(mybin, x.z, g.z); acc1px(mybin, x.w, g.w);
}

__global__ void __launch_bounds__(256, 8)
pass1_kernel(const float* __restrict__ f0, const float* __restrict__ f1,
             const float* __restrict__ f2, const int* __restrict__ g0,
             const int* __restrict__ g1, const int* __restrict__ g2) {
    __shared__ SmemU u;
    __shared__ int isLast;
    int tid = threadIdx.x;
    Map m = decode(f0, f1, f2, g0, g1, g2);

#pragma unroll
    for (int r = 0; r < 17; ++r) u.bins[r][tid] = 0;
    __syncthreads();

    int* mybin = &u.bins[0][tid];

#pragma unroll
    for (int it = 0; it < 2; ++it) {
        size_t i0 = m.base4 + (size_t)(it * 1024 + tid);
        float4 xa = m.f[i0];        float4 xb = m.f[i0 + 256];
        float4 xc = m.f[i0 + 512];  float4 xd = m.f[i0 + 768];
        int4 ga = m.g[i0];          int4 gb = m.g[i0 + 256];
        int4 gc = m.g[i0 + 512];    int4 gd = m.g[i0 + 768];
        acc1v(mybin, xa, ga); acc1v(mybin, xb, gb);
        acc1v(mybin, xc, gc); acc1v(mybin, xd, gd);
    }
    __syncthreads();

    // warp w reduces rows 2w, 2w+1 (rows 0..15 = labels 1..16)
    int w = tid >> 5, lane = tid & 31;
#pragma unroll
    for (int rr = 0; rr < 2; ++rr) {
        int row = 2 * w + rr;
        long long sq = 0;
        int sc = 0;
#pragma unroll
        for (int k = 0; k < 8; ++k) {
            int v = u.bins[row][lane + 32 * k];
            int c = v & 127;
            sc += c;
            sq += (long long)((v - c) >> 7);
        }
#pragma unroll
        for (int off = 16; off > 0; off >>= 1) {
            sq += __shfl_down_sync(0xffffffffu, sq, off);
            sc += __shfl_down_sync(0xffffffffu, sc, off);
        }
        if (lane == 0 && (sc | sq))
            atomicAdd(&g_bins1[m.scale * NSEG + m.batch * 17 + row + 1],
                      (((unsigned long long)(long long)sq) << CNT_BITS) +
                          (unsigned long long)sc);
    }

    // tail-CTA computes pooled means (release/acquire via threadfence+atomic)
    if (tid == 0) {
        __threadfence();
        isLast = (atomicAdd(&g_cnt1, 1) == NCTA - 1) ? 1 : 0;
    }
    __syncthreads();
    if (isLast) {
        if (tid == 0) g_cnt1 = 0;          // reset for next graph replay
        __threadfence();
        for (int sg = tid; sg < NSEG; sg += 256) {
            long long vs = 0, c = 0;
#pragma unroll
            for (int s = 0; s < 3; ++s) {
                long long raw = (long long)g_bins1[s * NSEG + sg];
                long long cnt = raw & CNT_MASK;
                vs += (raw - cnt) >> CNT_BITS;
                c += cnt;
            }
            g_mean[sg] = (c > 0) ? (float)((double)vs / (FPSCALE_D * (double)c)) : 0.0f;
        }
    }
}

// ---------------------------------------------------------------------------
__device__ __forceinline__ void acc2px(int* mybin, const float* msr, float xv, int gg) {
    unsigned row = min((unsigned)(gg - 1), 16u);
    float d = fmaxf(fabsf(xv - msr[row]) - 0.1f, 0.0f);
    mybin[row << 8] += __float2int_rn(d * d * FPSCALE_F);
}

__device__ __forceinline__ void acc2v(int* mybin, const float* msr, float4 x, int4 g) {
    acc2px(mybin, msr, x.x, g.x); acc2px(mybin, msr, x.y, g.y);
    acc2px(mybin, msr, x.z, g.z); acc2px(mybin, msr, x.w, g.w);
}

__global__ void __launch_bounds__(256, 8)
pass2_kernel(const float* __restrict__ f0, const float* __restrict__ f1,
             const float* __restrict__ f2, const int* __restrict__ g0,
             const int* __restrict__ g1, const int* __restrict__ g2,
             float* __restrict__ out) {
    __shared__ SmemU u;
    __shared__ float msr[17];
    __shared__ int isLast;
    int tid = threadIdx.x;
    Map m = decode(f0, f1, f2, g0, g1, g2);

#pragma unroll
    for (int r = 0; r < 17; ++r) u.bins[r][tid] = 0;
    if (tid < 16) msr[tid] = g_mean[m.batch * 17 + tid + 1];
    if (tid == 16) msr[16] = 0.0f;
    __syncthreads();

    int* mybin = &u.bins[0][tid];

    // REVERSE walk: re-read what pass1 most recently left in L2.
#pragma unroll
    for (int it = 1; it >= 0; --it) {
        size_t i0 = m.base4 + (size_t)(it * 1024 + tid);
        float4 xa = m.f[i0];        float4 xb = m.f[i0 + 256];
        float4 xc = m.f[i0 + 512];  float4 xd = m.f[i0 + 768];
        int4 ga = m.g[i0];          int4 gb = m.g[i0 + 256];
        int4 gc = m.g[i0 + 512];    int4 gd = m.g[i0 + 768];
        acc2v(mybin, msr, xd, gd); acc2v(mybin, msr, xc, gc);
        acc2v(mybin, msr, xb, gb); acc2v(mybin, msr, xa, ga);
    }
    __syncthreads();

    int w = tid >> 5, lane = tid & 31;
#pragma unroll
    for (int rr = 0; rr < 2; ++rr) {
        int row = 2 * w + rr;
        long long sq = 0;
#pragma unroll
        for (int k = 0; k < 8; ++k) sq += (long long)u.bins[row][lane + 32 * k];
#pragma unroll
        for (int off = 16; off > 0; off >>= 1)
            sq += __shfl_down_sync(0xffffffffu, sq, off);
        if (lane == 0 && sq)
            atomicAdd(&g_bins2[m.scale * NSEG + m.batch * 17 + row + 1],
                      (unsigned long long)sq);
    }

    // tail-CTA: final loss + self-clean all global state
    if (tid == 0) {
        __threadfence();
        isLast = (atomicAdd(&g_cnt2, 1) == NCTA - 1) ? 1 : 0;
    }
    __syncthreads();                        // also orders last bins reads
    if (!isLast) return;
    if (tid == 0) g_cnt2 = 0;
    __threadfence();

    // ---- epilogue (overlays bins storage; only tail CTA runs this) ----
    for (int sg = tid; sg < NSEG; sg += 256) {
        long long totc = 0;
        double ps = 0.0;
#pragma unroll
        for (int s = 0; s < 3; ++s) {
            long long raw = (long long)g_bins1[s * NSEG + sg];
            long long cnt = raw & CNT_MASK;
            totc += cnt;
            if (cnt > 0) {
                double ssum = (double)(long long)g_bins2[s * NSEG + sg] / FPSCALE_D;
                ps += ssum / (double)cnt;
            }
        }
        bool inst = (sg % 17) != 0;
        bool pres = inst && (totc > 0);
        u.epi.s_pres[sg] = (unsigned char)pres;
        u.epi.s_pull[sg] = pres ? ps : 0.0;
        u.epi.s_mean[sg] = g_mean[sg];
    }
    __syncthreads();

    double lv = 0.0;
    int ln = 0;
    for (int sg = tid; sg < NSEG; sg += 256)
        if (u.epi.s_pres[sg]) { lv += u.epi.s_pull[sg]; ln++; }

    double pv = 0.0;
    int pn = 0;
    {
        int b = tid >> 4, i = tid & 15;
        int segi = b * 17 + i + 1;
        if (u.epi.s_pres[segi]) {
            float mi = u.epi.s_mean[segi];
#pragma unroll
            for (int j = 0; j < 16; ++j) {
                if (j == i) continue;
                int segj = b * 17 + j + 1;
                if (u.epi.s_pres[segj]) {
                    float d = fmaxf(3.0f - fabsf(mi - u.epi.s_mean[segj]), 0.0f);
                    pv += (double)d * (double)d;
                    pn++;
                }
            }
        }
    }

    double pull_sum = 0.0;
    int n_pull = 0;
    u.epi.redv[tid] = lv; u.epi.redn[tid] = ln;
    __syncthreads();
    for (int s = 128; s > 0; s >>= 1) {
        if (tid < s) { u.epi.redv[tid] += u.epi.redv[tid + s]; u.epi.redn[tid] += u.epi.redn[tid + s]; }
        __syncthreads();
    }
    if (tid == 0) { pull_sum = u.epi.redv[0]; n_pull = u.epi.redn[0]; }
    __syncthreads();

    u.epi.redv[tid] = pv; u.epi.redn[tid] = pn;
    __syncthreads();
    for (int s = 128; s > 0; s >>= 1) {
        if (tid < s) { u.epi.redv[tid] += u.epi.redv[tid + s]; u.epi.redn[tid] += u.epi.redn[tid + s]; }
        __syncthreads();
    }
    if (tid == 0) {
        double push_sum = u.epi.redv[0];
        int n_push = u.epi.redn[0];
        double pull_loss = pull_sum / (double)(n_pull > 0 ? n_pull : 1);
        double push_loss = push_sum / (double)(n_push > 0 ? n_push : 1);
        out[0] = (float)(push_loss + pull_loss);
    }
    __syncthreads();
    // self-clean for next graph replay (after all reads above)
    for (int t = tid; t < 3 * NSEG; t += 256) {
        g_bins1[t] = 0ull;
        g_bins2[t] = 0ull;
    }
}

// ---------------------------------------------------------------------------
extern "C" void kernel_launch(void* const* d_in, const int* in_sizes, int n_in,
                              void* d_out, int out_size) {
    const float* f[3];
    const int* g[3];

    if (n_in >= 6 && in_sizes[0] == in_sizes[1]) {       // interleaved f,g pairs
        f[0] = (const float*)d_in[0]; g[0] = (const int*)d_in[1];
        f[1] = (const float*)d_in[2]; g[1] = (const int*)d_in[3];
        f[2] = (const float*)d_in[4]; g[2] = (const int*)d_in[5];
    } else {                                              // grouped
        f[0] = (const float*)d_in[0]; f[1] = (const float*)d_in[1];
        f[2] = (const float*)d_in[2];
        g[0] = (const int*)d_in[3]; g[1] = (const int*)d_in[4];
        g[2] = (const int*)d_in[5];
    }

    pass1_kernel<<<NCTA, 256>>>(f[0], f[1], f[2], g[0], g[1], g[2]);
    pass2_kernel<<<NCTA, 256>>>(f[0], f[1], f[2], g[0], g[1], g[2], (float*)d_out);
}

// round 8
// speedup vs baseline: 1.0365x; 1.0365x over previous
#include <cuda_runtime.h>
#include <cstdint>

// MSPushPullLoss — round 7.
// Falsified: reverse-walk L2 reuse (pass2 reverse = 46-48us at ANY occupancy;
// forward identical shape = 27us). Falsified: occupancy as binding constraint.
// This round: round-4 structure, both passes FORWARD, 16384-px chunks
// (grid 1344), no minCTA reg cap, smem union for fused epilogue.

#define NSEG 272                  // 16 batches * 17 labels (0..16)
#define CNT_BITS 21
#define CNT_MASK ((1ll << CNT_BITS) - 1)
#define FPSCALE_F 16384.0f        // q14 fixed point
#define FPSCALE_D 16384.0
#define NCTA (1024 + 256 + 64)    // 16384-px chunks

__device__ unsigned long long g_bins1[3 * NSEG];  // packed (sum_q14<<21 | count)
__device__ unsigned long long g_bins2[3 * NSEG];  // pull sum_q14
__device__ float g_mean[NSEG];
__device__ int g_cnt1;            // tail-CTA election counters (self-resetting)
__device__ int g_cnt2;

// ---------------------------------------------------------------------------
struct Map {
    const float4* f;
    const int4* g;
    int scale;
    size_t base4;   // float4 index of 4096-float4 chunk start
    int batch;
};

__device__ __forceinline__ Map decode(const float* f0, const float* f1, const float* f2,
                                      const int* g0, const int* g1, const int* g2) {
    Map m;
    int cid = blockIdx.x;
    if (cid < 1024) {
        m.scale = 0; m.f = (const float4*)f0; m.g = (const int4*)g0;
        m.batch = cid >> 6;
        m.base4 = (size_t)m.batch * (1u << 18) + (size_t)(cid & 63) * 4096u;
    } else if (cid < 1280) {
        int c = cid - 1024;
        m.scale = 1; m.f = (const float4*)f1; m.g = (const int4*)g1;
        m.batch = c >> 4;
        m.base4 = (size_t)m.batch * (1u << 16) + (size_t)(c & 15) * 4096u;
    } else {
        int c = cid - 1280;
        m.scale = 2; m.f = (const float4*)f2; m.g = (const int4*)g2;
        m.batch = c >> 2;
        m.base4 = (size_t)m.batch * (1u << 14) + (size_t)(c & 3) * 4096u;
    }
    return m;
}

// Shared-memory overlay: bins for the hot loop, epilogue arrays afterwards.
union SmemU {
    int bins[17][256];                      // 17408 B
    struct {
        double s_pull[NSEG];
        double redv[256];
        float s_mean[NSEG];
        int redn[256];
        unsigned char s_pres[NSEG];
    } epi;                                  // ~6608 B
};

// ---------------------------------------------------------------------------
__device__ __forceinline__ void acc1px(int* mybin, float xv, int gg) {
    unsigned row = min((unsigned)(gg - 1), 16u);   // row 16 = invalid dump
    int q = __float2int_rn(xv * FPSCALE_F);
    mybin[row << 8] += q * 128 + 1;                // (q<<7) | count (<=64/thread)
}

__device__ __forceinline__ void acc1v(int* mybin, float4 x, int4 g) {
    acc1px(mybin, x.x, g.x); acc1px(mybin, x.y, g.y);
    acc1px(mybin, x.z, g.z); acc1px(mybin, x.w, g.w);
}

__global__ void __launch_bounds__(256)
pass1_kernel(const float* __restrict__ f0, const float* __restrict__ f1,
             const float* __restrict__ f2, const int* __restrict__ g0,
             const int* __restrict__ g1, const int* __restrict__ g2) {
    __shared__ SmemU u;
    __shared__ int isLast;
    int tid = threadIdx.x;
    Map m = decode(f0, f1, f2, g0, g1, g2);

#pragma unroll
    for (int r = 0; r < 17; ++r) u.bins[r][tid] = 0;
    __syncthreads();

    int* mybin = &u.bins[0][tid];

#pragma unroll
    for (int it = 0; it < 4; ++it) {
        size_t i0 = m.base4 + (size_t)(it * 1024 + tid);
        float4 xa = m.f[i0];        float4 xb = m.f[i0 + 256];
        float4 xc = m.f[i0 + 512];  float4 xd = m.f[i0 + 768];
        int4 ga = m.g[i0];          int4 gb = m.g[i0 + 256];
        int4 gc = m.g[i0 + 512];    int4 gd = m.g[i0 + 768];
        acc1v(mybin, xa, ga); acc1v(mybin, xb, gb);
        acc1v(mybin, xc, gc); acc1v(mybin, xd, gd);
    }
    __syncthreads();

    // warp w reduces rows 2w, 2w+1 (rows 0..15 = labels 1..16)
    int w = tid >> 5, lane = tid & 31;
#pragma unroll
    for (int rr = 0; rr < 2; ++rr) {
        int row = 2 * w + rr;
        long long sq = 0;
        int sc = 0;
#pragma unroll
        for (int k = 0; k < 8; ++k) {
            int v = u.bins[row][lane + 32 * k];
            int c = v & 127;
            sc += c;
            sq += (long long)((v - c) >> 7);
        }
#pragma unroll
        for (int off = 16; off > 0; off >>= 1) {
            sq += __shfl_down_sync(0xffffffffu, sq, off);
            sc += __shfl_down_sync(0xffffffffu, sc, off);
        }
        if (lane == 0 && (sc | sq))
            atomicAdd(&g_bins1[m.scale * NSEG + m.batch * 17 + row + 1],
                      (((unsigned long long)(long long)sq) << CNT_BITS) +
                          (unsigned long long)sc);
    }

    // tail-CTA computes pooled means (release/acquire via threadfence+atomic)
    if (tid == 0) {
        __threadfence();
        isLast = (atomicAdd(&g_cnt1, 1) == NCTA - 1) ? 1 : 0;
    }
    __syncthreads();
    if (isLast) {
        if (tid == 0) g_cnt1 = 0;          // reset for next graph replay
        __threadfence();
        for (int sg = tid; sg < NSEG; sg += 256) {
            long long vs = 0, c = 0;
#pragma unroll
            for (int s = 0; s < 3; ++s) {
                long long raw = (long long)g_bins1[s * NSEG + sg];
                long long cnt = raw & CNT_MASK;
                vs += (raw - cnt) >> CNT_BITS;
                c += cnt;
            }
            g_mean[sg] = (c > 0) ? (float)((double)vs / (FPSCALE_D * (double)c)) : 0.0f;
        }
    }
}

// ---------------------------------------------------------------------------
__device__ __forceinline__ void acc2px(int* mybin, const float* msr, float xv, int gg) {
    unsigned row = min((unsigned)(gg - 1), 16u);
    float d = fmaxf(fabsf(xv - msr[row]) - 0.1f, 0.0f);
    mybin[row << 8] += __float2int_rn(d * d * FPSCALE_F);
}

__device__ __forceinline__ void acc2v(int* mybin, const float* msr, float4 x, int4 g) {
    acc2px(mybin, msr, x.x, g.x); acc2px(mybin, msr, x.y, g.y);
    acc2px(mybin, msr, x.z, g.z); acc2px(mybin, msr, x.w, g.w);
}

__global__ void __launch_bounds__(256)
pass2_kernel(const float* __restrict__ f0, const float* __restrict__ f1,
             const float* __restrict__ f2, const int* __restrict__ g0,
             const int* __restrict__ g1, const int* __restrict__ g2,
             float* __restrict__ out) {
    __shared__ SmemU u;
    __shared__ float msr[17];
    __shared__ int isLast;
    int tid = threadIdx.x;
    Map m = decode(f0, f1, f2, g0, g1, g2);

#pragma unroll
    for (int r = 0; r < 17; ++r) u.bins[r][tid] = 0;
    if (tid < 16) msr[tid] = g_mean[m.batch * 17 + tid + 1];
    if (tid == 16) msr[16] = 0.0f;
    __syncthreads();

    int* mybin = &u.bins[0][tid];

    // FORWARD walk (reverse measured 1.7x slower: defeats prefetch).
#pragma unroll
    for (int it = 0; it < 4; ++it) {
        size_t i0 = m.base4 + (size_t)(it * 1024 + tid);
        float4 xa = m.f[i0];        float4 xb = m.f[i0 + 256];
        float4 xc = m.f[i0 + 512];  float4 xd = m.f[i0 + 768];
        int4 ga = m.g[i0];          int4 gb = m.g[i0 + 256];
        int4 gc = m.g[i0 + 512];    int4 gd = m.g[i0 + 768];
        acc2v(mybin, msr, xa, ga); acc2v(mybin, msr, xb, gb);
        acc2v(mybin, msr, xc, gc); acc2v(mybin, msr, xd, gd);
    }
    __syncthreads();

    int w = tid >> 5, lane = tid & 31;
#pragma unroll
    for (int rr = 0; rr < 2; ++rr) {
        int row = 2 * w + rr;
        long long sq = 0;
#pragma unroll
        for (int k = 0; k < 8; ++k) sq += (long long)u.bins[row][lane + 32 * k];
#pragma unroll
        for (int off = 16; off > 0; off >>= 1)
            sq += __shfl_down_sync(0xffffffffu, sq, off);
        if (lane == 0 && sq)
            atomicAdd(&g_bins2[m.scale * NSEG + m.batch * 17 + row + 1],
                      (unsigned long long)sq);
    }

    // tail-CTA: final loss + self-clean all global state
    if (tid == 0) {
        __threadfence();
        isLast = (atomicAdd(&g_cnt2, 1) == NCTA - 1) ? 1 : 0;
    }
    __syncthreads();                        // also orders last bins reads
    if (!isLast) return;
    if (tid == 0) g_cnt2 = 0;
    __threadfence();

    // ---- epilogue (overlays bins storage; only tail CTA runs this) ----
    for (int sg = tid; sg < NSEG; sg += 256) {
        long long totc = 0;
        double ps = 0.0;
#pragma unroll
        for (int s = 0; s < 3; ++s) {
            long long raw = (long long)g_bins1[s * NSEG + sg];
            long long cnt = raw & CNT_MASK;
            totc += cnt;
            if (cnt > 0) {
                double ssum = (double)(long long)g_bins2[s * NSEG + sg] / FPSCALE_D;
                ps += ssum / (double)cnt;
            }
        }
        bool inst = (sg % 17) != 0;
        bool pres = inst && (totc > 0);
        u.epi.s_pres[sg] = (unsigned char)pres;
        u.epi.s_pull[sg] = pres ? ps : 0.0;
        u.epi.s_mean[sg] = g_mean[sg];
    }
    __syncthreads();

    double lv = 0.0;
    int ln = 0;
    for (int sg = tid; sg < NSEG; sg += 256)
        if (u.epi.s_pres[sg]) { lv += u.epi.s_pull[sg]; ln++; }

    double pv = 0.0;
    int pn = 0;
    {
        int b = tid >> 4, i = tid & 15;
        int segi = b * 17 + i + 1;
        if (u.epi.s_pres[segi]) {
            float mi = u.epi.s_mean[segi];
#pragma unroll
            for (int j = 0; j < 16; ++j) {
                if (j == i) continue;
                int segj = b * 17 + j + 1;
                if (u.epi.s_pres[segj]) {
                    float d = fmaxf(3.0f - fabsf(mi - u.epi.s_mean[segj]), 0.0f);
                    pv += (double)d * (double)d;
                    pn++;
                }
            }
        }
    }

    double pull_sum = 0.0;
    int n_pull = 0;
    u.epi.redv[tid] = lv; u.epi.redn[tid] = ln;
    __syncthreads();
    for (int s = 128; s > 0; s >>= 1) {
        if (tid < s) { u.epi.redv[tid] += u.epi.redv[tid + s]; u.epi.redn[tid] += u.epi.redn[tid + s]; }
        __syncthreads();
    }
    if (tid == 0) { pull_sum = u.epi.redv[0]; n_pull = u.epi.redn[0]; }
    __syncthreads();

    u.epi.redv[tid] = pv; u.epi.redn[tid] = pn;
    __syncthreads();
    for (int s = 128; s > 0; s >>= 1) {
        if (tid < s) { u.epi.redv[tid] += u.epi.redv[tid + s]; u.epi.redn[tid] += u.epi.redn[tid + s]; }
        __syncthreads();
    }
    if (tid == 0) {
        double push_sum = u.epi.redv[0];
        int n_push = u.epi.redn[0];
        double pull_loss = pull_sum / (double)(n_pull > 0 ? n_pull : 1);
        double push_loss = push_sum / (double)(n_push > 0 ? n_push : 1);
        out[0] = (float)(push_loss + pull_loss);
    }
    __syncthreads();
    // self-clean for next graph replay (after all reads above)
    for (int t = tid; t < 3 * NSEG; t += 256) {
        g_bins1[t] = 0ull;
        g_bins2[t] = 0ull;
    }
}

// ---------------------------------------------------------------------------
extern "C" void kernel_launch(void* const* d_in, const int* in_sizes, int n_in,
                              void* d_out, int out_size) {
    const float* f[3];
    const int* g[3];

    if (n_in >= 6 && in_sizes[0] == in_sizes[1]) {       // interleaved f,g pairs
        f[0] = (const float*)d_in[0]; g[0] = (const int*)d_in[1];
        f[1] = (const float*)d_in[2]; g[1] = (const int*)d_in[3];
        f[2] = (const float*)d_in[4]; g[2] = (const int*)d_in[5];
    } else {                                              // grouped
        f[0] = (const float*)d_in[0]; f[1] = (const float*)d_in[1];
        f[2] = (const float*)d_in[2];
        g[0] = (const int*)d_in[3]; g[1] = (const int*)d_in[4];
        g[2] = (const int*)d_in[5];
    }

    pass1_kernel<<<NCTA, 256>>>(f[0], f[1], f[2], g[0], g[1], g[2]);
    pass2_kernel<<<NCTA, 256>>>(f[0], f[1], f[2], g[0], g[1], g[2], (float*)d_out);
}